// round 12
// baseline (speedup 1.0000x reference)
#include <cuda_runtime.h>
#include <cstdint>

// ---------------------------------------------------------------------------
// Problem constants
// ---------------------------------------------------------------------------
#define BATCH 32
#define TIME 1024
#define IN_DIM 512
#define HIDDEN 512

#define M_TOTAL (BATCH * TIME)   // 32768
#define N_TOTAL HIDDEN           // 512
#define K_TOTAL IN_DIM           // 512

#define ALPHA_MEM 0.95122942450071400909f  // exp(-0.05)
#define ALPHA_SYN 0.81873075307798185867f  // exp(-0.2)
#define THRESHOLD 1.0f

// Scratch for I_in = spikes @ W + b : [B*T, H] = 64 MB
__device__ float g_Iin[(size_t)M_TOTAL * N_TOTAL];

typedef unsigned long long u64;

__device__ __forceinline__ void fma2(u64& d, u64 a, u64 b) {
    asm("fma.rn.f32x2 %0, %1, %2, %3;" : "=l"(d) : "l"(a), "l"(b), "l"(d));
}
__device__ __forceinline__ u64 add2(u64 a, u64 b) {
    u64 r;
    asm("add.rn.f32x2 %0, %1, %2;" : "=l"(r) : "l"(a), "l"(b));
    return r;
}

// ---------------------------------------------------------------------------
// fp32 GEMM, reference-matching semantics: each output (m,n) is ONE fp32 FMA
// chain over k = 0..511 ascending, bias added once at the end. (This order
// bit-matches the reference einsum's per-output accumulation; verified by
// rel_err == 0.0 in rounds 1-2.)
//
// 128x128 CTA tile, BK=16, 256 threads, 8x8 micro-tile as 8 x 4 FFMA2
// (acc pairs over n). A is staged in smem TRANSPOSED AND DUPLICATED
// (As2[k][m] = (a,a)) so the broadcast operand of FFMA2 loads directly with
// LDS.128 — no per-k packing movs. 24 KB smem/CTA -> 2 CTAs/SM.
// ---------------------------------------------------------------------------
#define BM 128
#define BN 128
#define BK 16
#define TM 8
#define TN 8
#define APITCH 130   // float2 pitch of As2 rows (16B aligned, breaks conflicts)

__global__ __launch_bounds__(256, 2)
void gemm_f32_kernel(const float* __restrict__ A,
                     const float* __restrict__ W,
                     const float* __restrict__ bias,
                     float* __restrict__ C)
{
    __shared__ float2 As2[BK * APITCH];      // dup pairs: As2[k*APITCH + m] = (a,a)
    __shared__ float  Bs[BK][BN + 4];

    const int bm = blockIdx.y * BM;
    const int bn = blockIdx.x * BN;
    const int tid = threadIdx.x;           // 0..255
    const int tx = tid & 15;               // n micro-tile
    const int ty = tid >> 4;               // m micro-tile

    // A-load mapping: 128 rows x 16 cols, float4 per thread, 2 passes
    const int arow = tid >> 2;             // 0..63
    const int acol = (tid & 3) << 2;       // 0,4,8,12
    // B-load mapping: 16 rows x 128 cols, float4 per thread, 2 passes
    const int brow = tid >> 5;             // 0..7
    const int bcol = (tid & 31) << 2;      // 0..124

    u64 acc[TM][TN / 2];
#pragma unroll
    for (int i = 0; i < TM; i++)
#pragma unroll
        for (int j = 0; j < TN / 2; j++)
            acc[i][j] = 0ULL;

    const float* Aptr = A + (size_t)bm * K_TOTAL;
    const float* Wptr = W + bn;

    for (int k0 = 0; k0 < K_TOTAL; k0 += BK) {
        // Load A tile; transpose + duplicate into As2
#pragma unroll
        for (int r = 0; r < 2; r++) {
            const int m = arow + r * 64;
            float4 v = *(const float4*)(Aptr + (size_t)m * K_TOTAL + k0 + acol);
            As2[(acol + 0) * APITCH + m] = make_float2(v.x, v.x);
            As2[(acol + 1) * APITCH + m] = make_float2(v.y, v.y);
            As2[(acol + 2) * APITCH + m] = make_float2(v.z, v.z);
            As2[(acol + 3) * APITCH + m] = make_float2(v.w, v.w);
        }
        // Load B tile (natural [k][n])
#pragma unroll
        for (int r = 0; r < 2; r++) {
            float4 v = *(const float4*)(Wptr + (size_t)(k0 + brow + r * 8) * N_TOTAL + bcol);
            *(float4*)(&Bs[brow + r * 8][bcol]) = v;
        }
        __syncthreads();

#pragma unroll
        for (int k = 0; k < BK; k++) {
            // a: 8 dup-pairs via 4 x LDS.128
            const ulonglong2* ap128 = (const ulonglong2*)(&As2[k * APITCH + ty * TM]);
            ulonglong2 aq0 = ap128[0];
            ulonglong2 aq1 = ap128[1];
            ulonglong2 aq2 = ap128[2];
            ulonglong2 aq3 = ap128[3];
            u64 ap[TM] = { aq0.x, aq0.y, aq1.x, aq1.y, aq2.x, aq2.y, aq3.x, aq3.y };
            // b: 4 natural pairs via 2 x LDS.128
            ulonglong2 bq0 = *(const ulonglong2*)(&Bs[k][tx * TN]);
            ulonglong2 bq1 = *(const ulonglong2*)(&Bs[k][tx * TN + 4]);
            u64 bp0 = bq0.x, bp1 = bq0.y, bp2 = bq1.x, bp3 = bq1.y;
#pragma unroll
            for (int i = 0; i < TM; i++) {
                fma2(acc[i][0], ap[i], bp0);
                fma2(acc[i][1], ap[i], bp1);
                fma2(acc[i][2], ap[i], bp2);
                fma2(acc[i][3], ap[i], bp3);
            }
        }
        __syncthreads();
    }

    // Epilogue: packed bias add (one fp32 add per output, matching reference),
    // 16B stores.
    ulonglong2 bv0 = *(const ulonglong2*)(bias + bn + tx * TN);
    ulonglong2 bv1 = *(const ulonglong2*)(bias + bn + tx * TN + 4);
#pragma unroll
    for (int i = 0; i < TM; i++) {
        float* crow = C + (size_t)(bm + ty * TM + i) * N_TOTAL + bn + tx * TN;
        ulonglong2 o0, o1;
        o0.x = add2(acc[i][0], bv0.x);
        o0.y = add2(acc[i][1], bv0.y);
        o1.x = add2(acc[i][2], bv1.x);
        o1.y = add2(acc[i][3], bv1.y);
        *(ulonglong2*)(crow) = o0;
        *(ulonglong2*)(crow + 4) = o1;
    }
}

// ---------------------------------------------------------------------------
// LIF scan: 1 neuron per thread, serial over T. 64-thread blocks -> 256
// blocks (~3.4 warps/SM). U=32 double-buffered scalar prefetch for MLP.
// Arithmetic identical to the round-1/2 passing version (fmaf chain).
// ---------------------------------------------------------------------------
#define SU 32

__global__ __launch_bounds__(64)
void lif_scan_kernel(const float* __restrict__ Iin, float* __restrict__ out) {
    const int g = blockIdx.x * 64 + threadIdx.x;   // 0 .. B*H-1
    const int b = g >> 9;                          // / HIDDEN
    const int h = g & (HIDDEN - 1);

    const float* p = Iin + (size_t)b * TIME * HIDDEN + h;
    float* q = out + (size_t)b * TIME * HIDDEN + h;

    float bufA[SU], bufB[SU];
#pragma unroll
    for (int i = 0; i < SU; i++)
        bufA[i] = __ldcs(p + (size_t)i * HIDDEN);

    float v = 0.0f, s = 0.0f;

    for (int t0 = 0; t0 < TIME; t0 += 2 * SU) {
        if (t0 + SU < TIME) {
#pragma unroll
            for (int i = 0; i < SU; i++)
                bufB[i] = __ldcs(p + (size_t)(t0 + SU + i) * HIDDEN);
        }
#pragma unroll
        for (int i = 0; i < SU; i++) {
            s = fmaf(ALPHA_SYN, s, bufA[i]);
            v = fmaf(ALPHA_MEM, v, s);
            float o = (v > THRESHOLD) ? 1.0f : 0.0f;
            v -= o;
            __stcs(q + (size_t)(t0 + i) * HIDDEN, o);
        }
        if (t0 + 2 * SU < TIME) {
#pragma unroll
            for (int i = 0; i < SU; i++)
                bufA[i] = __ldcs(p + (size_t)(t0 + 2 * SU + i) * HIDDEN);
        }
#pragma unroll
        for (int i = 0; i < SU; i++) {
            s = fmaf(ALPHA_SYN, s, bufB[i]);
            v = fmaf(ALPHA_MEM, v, s);
            float o = (v > THRESHOLD) ? 1.0f : 0.0f;
            v -= o;
            __stcs(q + (size_t)(t0 + SU + i) * HIDDEN, o);
        }
    }
}

// ---------------------------------------------------------------------------
extern "C" void kernel_launch(void* const* d_in, const int* in_sizes, int n_in,
                              void* d_out, int out_size)
{
    const float* spikes = (const float*)d_in[0];  // [B, T, I]
    const float* W      = (const float*)d_in[1];  // [I, H]
    const float* bias   = (const float*)d_in[2];  // [H]
    float* out          = (float*)d_out;          // [B, T, H]

    float* Iin;
    cudaGetSymbolAddress((void**)&Iin, g_Iin);

    dim3 ggrid(N_TOTAL / BN, M_TOTAL / BM);  // (4, 256)
    gemm_f32_kernel<<<ggrid, 256>>>(spikes, W, bias, Iin);

    lif_scan_kernel<<<(BATCH * HIDDEN) / 64, 64>>>(Iin, out);
}